// round 5
// baseline (speedup 1.0000x reference)
#include <cuda_runtime.h>
#include <math.h>

#define N_REGS 32
#define KEY_DIM 128
#define BIT_WIDTH 64
#define TAB_VEC4 (N_REGS * BIT_WIDTH / 4)   // 512
#define THREADS 256
#define GRID 1184                            // 148 SMs * 8 CTAs = one full wave
#define UNROLL 4
#define FLAG_STRIDE 32                       // 32 uints = 128B line per flag copy

// Precomputed output table: one 64-float row per idx value. 8 KB.
__device__ float g_table[N_REGS * BIT_WIDTH];
// Handshake state. Each flag copy / counter sits on its own 128B line so
// poll reads never contend with the builders' RMWs on one LTS slice.
__device__ __align__(128) unsigned g_go_arr[N_REGS * FLAG_STRIDE];  // 4 KB, zero-init
__device__ __align__(128) unsigned g_ready[FLAG_STRIDE];
__device__ __align__(128) unsigned g_done[FLAG_STRIDE];

__device__ __forceinline__ float gelu_exact(float x) {
    // 0.5 * x * (1 + erf(x / sqrt(2)))  — matches jax.nn.gelu(approximate=False)
    return 0.5f * x * (1.0f + erff(x * 0.70710678118654752440f));
}

__global__ void __launch_bounds__(THREADS, 8) fused_kernel(
    const int*   __restrict__ idx,
    const float* __restrict__ W1,          // [5, 128]
    const float* __restrict__ b1,          // [128]
    const float* __restrict__ W2,          // [128, 128]
    const float* __restrict__ b2,          // [128]
    const float* __restrict__ keys,        // [32, 128]
    const float* __restrict__ temperature, // scalar
    const float* __restrict__ rv,          // [32, 64]
    float4*      __restrict__ out,
    int total_vec4)                        // = B * 16
{
    __shared__ float4 stab[TAB_VEC4];      // 8 KB staged table

    const int tid = threadIdx.x;

    // ------------- Producer phase: blocks 0..31 build one table row each ----
    if (blockIdx.x < N_REGS) {
        __shared__ float sh_h[KEY_DIM];
        __shared__ float sh_q[KEY_DIM];
        __shared__ float sh_a[N_REGS];

        const int idv = (int)blockIdx.x;

        // h = gelu(bits @ W1 + b1)
        if (tid < KEY_DIM) {
            float acc = b1[tid];
            #pragma unroll
            for (int k = 0; k < 5; k++)
                if ((idv >> k) & 1) acc += W1[k * KEY_DIM + tid];
            sh_h[tid] = gelu_exact(acc);
        }
        __syncthreads();

        // query = h @ W2 + b2 (coalesced across tid; unroll 8 -> MLP 8)
        if (tid < KEY_DIM) {
            float q = b2[tid];
            #pragma unroll 8
            for (int j = 0; j < KEY_DIM; j++)
                q = fmaf(sh_h[j], W2[j * KEY_DIM + tid], q);
            sh_q[tid] = q;
        }
        __syncthreads();

        // sim[r] = q . keys[r], 4 lanes per register row (threads 0..127)
        if (tid < 128) {
            int r = tid >> 2, part = tid & 3;
            float s = 0.0f;
            #pragma unroll 8
            for (int i = part * 32; i < part * 32 + 32; i++)
                s = fmaf(sh_q[i], keys[r * KEY_DIM + i], s);
            s += __shfl_xor_sync(0xffffffffu, s, 1);
            s += __shfl_xor_sync(0xffffffffu, s, 2);
            if (part == 0) sh_a[r] = s;
        }
        __syncthreads();

        // softmax over 32 (warp 0)
        if (tid < N_REGS) {
            float temp = fmaxf(fabsf(temperature[0]), 0.1f);
            float s = sh_a[tid] / temp;
            float m = s;
            #pragma unroll
            for (int off = 16; off > 0; off >>= 1)
                m = fmaxf(m, __shfl_xor_sync(0xffffffffu, m, off));
            float e = expf(s - m);
            float sum = e;
            #pragma unroll
            for (int off = 16; off > 0; off >>= 1)
                sum += __shfl_xor_sync(0xffffffffu, sum, off);
            sh_a[tid] = e / sum;
        }
        __syncthreads();

        // table row = attn @ register_values; XZR (idx==31) forced to zero
        if (tid < BIT_WIDTH) {
            float v = 0.0f;
            #pragma unroll
            for (int r = 0; r < N_REGS; r++)
                v = fmaf(sh_a[r], rv[r * BIT_WIDTH + tid], v);
            if (idv == 31) v = 0.0f;
            g_table[idv * BIT_WIDTH + tid] = v;
        }
        __syncthreads();
        __threadfence();                      // publish table row to L2
        if (tid == 0) {
            unsigned prev = atomicAdd(&g_ready[0], 1u);
            if (prev == N_REGS - 1) {
                __threadfence();
                // release: fan the flag out across 32 distinct lines
                for (int f = 0; f < N_REGS; f++)
                    *(volatile unsigned*)&g_go_arr[f * FLAG_STRIDE] = 1u;
            }
        }
    }

    // ------------- Handshake: sharded plain-load poll with backoff -----------
    if (tid == 0) {
        volatile unsigned* flag = &g_go_arr[(blockIdx.x & (N_REGS - 1)) * FLAG_STRIDE];
        unsigned delay = 64u + ((blockIdx.x >> 5) & 15u) * 16u;  // stagger phases
        while (*flag == 0u) {
            __nanosleep(delay);
            delay = min(delay * 2u, 1024u);
        }
    }
    __syncthreads();

    // Stage table into smem. __ldcg bypasses L1 -> coherent with builders' L2 data.
    const float4* gt = reinterpret_cast<const float4*>(g_table);
    for (int i = tid; i < TAB_VEC4; i += THREADS)
        stab[i] = __ldcg(&gt[i]);
    __syncthreads();

    // ------------- Consumer phase: persistent grid-stride gather -------------
    // Thread element stride = GRID*THREADS (0 mod 16) so c = t & 15 is constant:
    // stores stay fully coalesced, smem reads conflict-free.
    const int step = GRID * THREADS;
    int base = (int)blockIdx.x * THREADS + tid;

    for (; base + (UNROLL - 1) * step < total_vec4; base += UNROLL * step) {
        int r[UNROLL];
        #pragma unroll
        for (int u = 0; u < UNROLL; u++)
            r[u] = __ldg(&idx[(base + u * step) >> 4]);    // MLP=UNROLL
        float4 v[UNROLL];
        #pragma unroll
        for (int u = 0; u < UNROLL; u++)
            v[u] = stab[(r[u] << 4) + ((base + u * step) & 15)];
        #pragma unroll
        for (int u = 0; u < UNROLL; u++)
            out[base + u * step] = v[u];                   // plain STG.128
    }
    for (; base < total_vec4; base += step) {
        int rr = __ldg(&idx[base >> 4]);
        out[base] = stab[(rr << 4) + (base & 15)];
    }

    // ------------- Reset flags for the next graph replay ---------------------
    __syncthreads();
    if (tid == 0) {
        unsigned old = atomicAdd(&g_done[0], 1u);
        if (old == (unsigned)(gridDim.x - 1)) {
            for (int f = 0; f < N_REGS; f++)
                *(volatile unsigned*)&g_go_arr[f * FLAG_STRIDE] = 0u;
            atomicExch(&g_ready[0], 0u);
            atomicExch(&g_done[0], 0u);
            __threadfence();
        }
    }
}

extern "C" void kernel_launch(void* const* d_in, const int* in_sizes, int n_in,
                              void* d_out, int out_size)
{
    const int*   idx  = (const int*)  d_in[0];
    const float* W1   = (const float*)d_in[1];
    const float* b1   = (const float*)d_in[2];
    const float* W2   = (const float*)d_in[3];
    const float* b2   = (const float*)d_in[4];
    const float* keys = (const float*)d_in[5];
    const float* temp = (const float*)d_in[6];
    const float* rv   = (const float*)d_in[7];

    const int B = in_sizes[0];
    const int total_vec4 = B * (BIT_WIDTH / 4);   // B * 16

    fused_kernel<<<GRID, THREADS>>>(idx, W1, b1, W2, b2, keys, temp, rv,
                                    (float4*)d_out, total_vec4);
}

// round 6
// speedup vs baseline: 1.1453x; 1.1453x over previous
#include <cuda_runtime.h>
#include <math.h>

#define N_REGS 32
#define KEY_DIM 128
#define BIT_WIDTH 64
#define TAB_VEC4 (N_REGS * BIT_WIDTH / 4)   // 512
#define THREADS 256
#define GRID 888                             // 148 SMs * 6 CTAs = one resident wave
#define UNROLL 4
#define FLAG_STRIDE 32                       // one 128B line per flag copy

// Precomputed output table: one 64-float row per idx value. 8 KB.
__device__ float g_table[N_REGS * BIT_WIDTH];
// Handshake state, each element on its own 128B line.
__device__ __align__(128) unsigned g_go_arr[N_REGS * FLAG_STRIDE];
__device__ __align__(128) unsigned g_ready[FLAG_STRIDE];
__device__ __align__(128) unsigned g_done[FLAG_STRIDE];

__device__ __forceinline__ float gelu_exact(float x) {
    return 0.5f * x * (1.0f + erff(x * 0.70710678118654752440f));
}

__device__ __forceinline__ void l2_prefetch(const void* p) {
    asm volatile("prefetch.global.L2 [%0];" :: "l"(p));
}

__global__ void __launch_bounds__(THREADS, 6) fused_kernel(
    const int*   __restrict__ idx,
    const float* __restrict__ W1,          // [5, 128]
    const float* __restrict__ b1,          // [128]
    const float* __restrict__ W2,          // [128, 128]
    const float* __restrict__ b2,          // [128]
    const float* __restrict__ keys,        // [32, 128]
    const float* __restrict__ temperature, // scalar
    const float* __restrict__ rv,          // [32, 64]
    float4*      __restrict__ out,
    int total_vec4)                        // = B * 16
{
    __shared__ float4 stab[TAB_VEC4];      // 8 KB staged table

    const int tid = threadIdx.x;

    // ------------- Producer phase: blocks 0..31 build one table row each ----
    if (blockIdx.x < N_REGS) {
        __shared__ float sh_h[KEY_DIM];
        __shared__ float sh_qp[2 * KEY_DIM];   // split-j partials
        __shared__ float sh_a[N_REGS];

        // 0) Fire-and-forget L2 prefetch of every weight line (MLP = huge,
        //    zero register pressure, no dependencies). W2: 512 lines,
        //    keys: 128 lines, rv: 64 lines.
        l2_prefetch((const char*)W2 + tid * 256);          // 2 lines/thread
        l2_prefetch((const char*)W2 + tid * 256 + 128);
        if (tid < 128) l2_prefetch((const char*)keys + tid * 128);
        if (tid >= 128 && tid < 192) l2_prefetch((const char*)rv + (tid - 128) * 128);

        const int idv = (int)blockIdx.x;

        // 1) h = gelu(bits @ W1 + b1)
        if (tid < KEY_DIM) {
            float acc = b1[tid];
            #pragma unroll
            for (int k = 0; k < 5; k++)
                if ((idv >> k) & 1) acc += W1[k * KEY_DIM + tid];
            sh_h[tid] = gelu_exact(acc);
        }
        __syncthreads();

        // 2) query = h @ W2 + b2, all 256 threads: o = tid&127, half = tid>>7
        {
            const int o = tid & 127, half = tid >> 7;
            float part = (half == 0) ? b2[o] : 0.0f;
            const int j0 = half * 64;
            #pragma unroll 16
            for (int j = j0; j < j0 + 64; j++)
                part = fmaf(sh_h[j], W2[j * KEY_DIM + o], part);
            sh_qp[half * KEY_DIM + o] = part;
        }
        __syncthreads();
        if (tid < KEY_DIM)
            sh_qp[tid] = sh_qp[tid] + sh_qp[KEY_DIM + tid];
        __syncthreads();

        // 3) sim[r] = q . keys[r], 8 lanes per register row (256 threads)
        {
            const int r = tid >> 3, part = tid & 7;
            float s = 0.0f;
            #pragma unroll 16
            for (int i = part * 16; i < part * 16 + 16; i++)
                s = fmaf(sh_qp[i], keys[r * KEY_DIM + i], s);
            s += __shfl_xor_sync(0xffffffffu, s, 1);
            s += __shfl_xor_sync(0xffffffffu, s, 2);
            s += __shfl_xor_sync(0xffffffffu, s, 4);
            if (part == 0) sh_a[r] = s;
        }
        __syncthreads();

        // 4) softmax over 32 (warp 0)
        if (tid < N_REGS) {
            float temp = fmaxf(fabsf(temperature[0]), 0.1f);
            float s = sh_a[tid] / temp;
            float m = s;
            #pragma unroll
            for (int off = 16; off > 0; off >>= 1)
                m = fmaxf(m, __shfl_xor_sync(0xffffffffu, m, off));
            float e = expf(s - m);
            float sum = e;
            #pragma unroll
            for (int off = 16; off > 0; off >>= 1)
                sum += __shfl_xor_sync(0xffffffffu, sum, off);
            sh_a[tid] = e / sum;
        }
        __syncthreads();

        // 5) table row = attn @ register_values; XZR (idx==31) forced to zero
        if (tid < BIT_WIDTH) {
            float v = 0.0f;
            #pragma unroll
            for (int r = 0; r < N_REGS; r++)
                v = fmaf(sh_a[r], rv[r * BIT_WIDTH + tid], v);
            if (idv == 31) v = 0.0f;
            g_table[idv * BIT_WIDTH + tid] = v;
        }
        __syncthreads();
        __threadfence();                      // publish table row to L2
        if (tid == 0) {
            unsigned prev = atomicAdd(&g_ready[0], 1u);
            if (prev == N_REGS - 1) {
                __threadfence();
                for (int f = 0; f < N_REGS; f++)
                    *(volatile unsigned*)&g_go_arr[f * FLAG_STRIDE] = 1u;
            }
        }
    } else {
        // Consumers: prefetch our idx slice into L2 while we wait (4 MB total).
        const int nrows = total_vec4 >> 4;
        const int wpb = (nrows + GRID - 1) / GRID;
        const int s0 = (int)blockIdx.x * wpb;
        for (int w = s0 + tid * 32; w < s0 + wpb && w < nrows; w += THREADS * 32)
            l2_prefetch(idx + w);
    }

    // ------------- Handshake: sharded plain-load poll with backoff -----------
    if (tid == 0) {
        volatile unsigned* flag = &g_go_arr[(blockIdx.x & (N_REGS - 1)) * FLAG_STRIDE];
        unsigned delay = 64u + ((blockIdx.x >> 5) & 15u) * 16u;
        while (*flag == 0u) {
            __nanosleep(delay);
            delay = min(delay * 2u, 1024u);
        }
    }
    __syncthreads();

    // Stage table into smem (__ldcg: L1-bypass, coherent with builders' L2 data).
    const float4* gt = reinterpret_cast<const float4*>(g_table);
    for (int i = tid; i < TAB_VEC4; i += THREADS)
        stab[i] = __ldcg(&gt[i]);
    __syncthreads();

    // ------------- Consumer phase: persistent grid-stride gather -------------
    // Element stride = GRID*THREADS (0 mod 16): c = t & 15 constant per thread,
    // stores fully coalesced, smem reads conflict-free.
    const int step = GRID * THREADS;
    int base = (int)blockIdx.x * THREADS + tid;

    for (; base + (UNROLL - 1) * step < total_vec4; base += UNROLL * step) {
        int r[UNROLL];
        #pragma unroll
        for (int u = 0; u < UNROLL; u++)
            r[u] = __ldg(&idx[(base + u * step) >> 4]);    // MLP=UNROLL
        float4 v[UNROLL];
        #pragma unroll
        for (int u = 0; u < UNROLL; u++)
            v[u] = stab[(r[u] << 4) + ((base + u * step) & 15)];
        #pragma unroll
        for (int u = 0; u < UNROLL; u++)
            out[base + u * step] = v[u];                   // plain STG.128
    }
    for (; base < total_vec4; base += step) {
        int rr = __ldg(&idx[base >> 4]);
        out[base] = stab[(rr << 4) + (base & 15)];
    }

    // ------------- Reset flags for the next graph replay ---------------------
    __syncthreads();
    if (tid == 0) {
        unsigned old = atomicAdd(&g_done[0], 1u);
        if (old == (unsigned)(gridDim.x - 1)) {
            for (int f = 0; f < N_REGS; f++)
                *(volatile unsigned*)&g_go_arr[f * FLAG_STRIDE] = 0u;
            atomicExch(&g_ready[0], 0u);
            atomicExch(&g_done[0], 0u);
            __threadfence();
        }
    }
}

extern "C" void kernel_launch(void* const* d_in, const int* in_sizes, int n_in,
                              void* d_out, int out_size)
{
    const int*   idx  = (const int*)  d_in[0];
    const float* W1   = (const float*)d_in[1];
    const float* b1   = (const float*)d_in[2];
    const float* W2   = (const float*)d_in[3];
    const float* b2   = (const float*)d_in[4];
    const float* keys = (const float*)d_in[5];
    const float* temp = (const float*)d_in[6];
    const float* rv   = (const float*)d_in[7];

    const int B = in_sizes[0];
    const int total_vec4 = B * (BIT_WIDTH / 4);   // B * 16

    fused_kernel<<<GRID, THREADS>>>(idx, W1, b1, W2, b2, keys, temp, rv,
                                    (float4*)d_out, total_vec4);
}

// round 7
// speedup vs baseline: 1.1756x; 1.0264x over previous
#include <cuda_runtime.h>
#include <math.h>

#define N_REGS 32
#define KEY_DIM 128
#define BIT_WIDTH 64
#define TAB_VEC4 (N_REGS * BIT_WIDTH / 4)   // 512
#define THREADS 256
#define GRID 888                             // 148 SMs * 6 CTAs = one resident wave
#define UNROLL 8
#define FLAG_STRIDE 32                       // one 128B line per flag copy

// Precomputed output table: one 64-float row per idx value. 8 KB.
__device__ float g_table[N_REGS * BIT_WIDTH];
// Handshake state, each element on its own 128B line.
__device__ __align__(128) unsigned g_go_arr[N_REGS * FLAG_STRIDE];
__device__ __align__(128) unsigned g_ready[FLAG_STRIDE];
__device__ __align__(128) unsigned g_done[FLAG_STRIDE];

__device__ __forceinline__ float gelu_exact(float x) {
    return 0.5f * x * (1.0f + erff(x * 0.70710678118654752440f));
}

__device__ __forceinline__ void l2_prefetch(const void* p) {
    asm volatile("prefetch.global.L2 [%0];" :: "l"(p));
}

__global__ void __launch_bounds__(THREADS, 6) fused_kernel(
    const int*   __restrict__ idx,
    const float* __restrict__ W1,          // [5, 128]
    const float* __restrict__ b1,          // [128]
    const float* __restrict__ W2,          // [128, 128]
    const float* __restrict__ b2,          // [128]
    const float* __restrict__ keys,        // [32, 128]
    const float* __restrict__ temperature, // scalar
    const float* __restrict__ rv,          // [32, 64]
    float4*      __restrict__ out,
    int total_vec4)                        // = B * 16
{
    __shared__ float4 stab[TAB_VEC4];      // 8 KB staged table

    const int tid = threadIdx.x;
    const int step = GRID * THREADS;
    int base = (int)blockIdx.x * THREADS + tid;

    // ------------- Producer phase: blocks 0..31 build one table row each ----
    if (blockIdx.x < N_REGS) {
        __shared__ float sh_h[KEY_DIM];
        __shared__ float sh_qp[2 * KEY_DIM];   // split-j partials
        __shared__ float sh_a[N_REGS];

        // 0) Fire-and-forget L2 prefetch of every weight line.
        l2_prefetch((const char*)W2 + tid * 256);          // 2 lines/thread
        l2_prefetch((const char*)W2 + tid * 256 + 128);
        if (tid < 128) l2_prefetch((const char*)keys + tid * 128);
        if (tid >= 128 && tid < 192) l2_prefetch((const char*)rv + (tid - 128) * 128);

        const int idv = (int)blockIdx.x;

        // 1) h = gelu(bits @ W1 + b1)
        if (tid < KEY_DIM) {
            float acc = b1[tid];
            #pragma unroll
            for (int k = 0; k < 5; k++)
                if ((idv >> k) & 1) acc += W1[k * KEY_DIM + tid];
            sh_h[tid] = gelu_exact(acc);
        }
        __syncthreads();

        // 2) query = h @ W2 + b2, split-j across all 256 threads
        {
            const int o = tid & 127, half = tid >> 7;
            float part = (half == 0) ? b2[o] : 0.0f;
            const int j0 = half * 64;
            #pragma unroll 16
            for (int j = j0; j < j0 + 64; j++)
                part = fmaf(sh_h[j], W2[j * KEY_DIM + o], part);
            sh_qp[half * KEY_DIM + o] = part;
        }
        __syncthreads();
        if (tid < KEY_DIM)
            sh_qp[tid] = sh_qp[tid] + sh_qp[KEY_DIM + tid];
        __syncthreads();

        // 3) sim[r] = q . keys[r], 8 lanes per register row
        {
            const int r = tid >> 3, part = tid & 7;
            float s = 0.0f;
            #pragma unroll 16
            for (int i = part * 16; i < part * 16 + 16; i++)
                s = fmaf(sh_qp[i], keys[r * KEY_DIM + i], s);
            s += __shfl_xor_sync(0xffffffffu, s, 1);
            s += __shfl_xor_sync(0xffffffffu, s, 2);
            s += __shfl_xor_sync(0xffffffffu, s, 4);
            if (part == 0) sh_a[r] = s;
        }
        __syncthreads();

        // 4) softmax over 32 (warp 0)
        if (tid < N_REGS) {
            float temp = fmaxf(fabsf(temperature[0]), 0.1f);
            float s = sh_a[tid] / temp;
            float m = s;
            #pragma unroll
            for (int off = 16; off > 0; off >>= 1)
                m = fmaxf(m, __shfl_xor_sync(0xffffffffu, m, off));
            float e = expf(s - m);
            float sum = e;
            #pragma unroll
            for (int off = 16; off > 0; off >>= 1)
                sum += __shfl_xor_sync(0xffffffffu, sum, off);
            sh_a[tid] = e / sum;
        }
        __syncthreads();

        // 5) table row = attn @ register_values; XZR (idx==31) forced to zero
        if (tid < BIT_WIDTH) {
            float v = 0.0f;
            #pragma unroll
            for (int r = 0; r < N_REGS; r++)
                v = fmaf(sh_a[r], rv[r * BIT_WIDTH + tid], v);
            if (idv == 31) v = 0.0f;
            g_table[idv * BIT_WIDTH + tid] = v;
        }
        __syncthreads();
        __threadfence();                      // publish table row to L2
        if (tid == 0) {
            unsigned prev = atomicAdd(&g_ready[0], 1u);
            if (prev == N_REGS - 1) {
                __threadfence();
                for (int f = 0; f < N_REGS; f++)
                    *(volatile unsigned*)&g_go_arr[f * FLAG_STRIDE] = 1u;
            }
        }
    } else {
        // Consumers: warm L2 with our idx slice while we wait (4 MB total).
        const int nrows = total_vec4 >> 4;
        const int wpb = (nrows + GRID - 1) / GRID;
        const int s0 = (int)blockIdx.x * wpb;
        for (int w = s0 + tid * 32; w < s0 + wpb && w < nrows; w += THREADS * 32)
            l2_prefetch(idx + w);
    }

    // Pre-load the FIRST idx batch into registers before polling: these are
    // table-independent inputs, so when the flag lands we go straight to
    // LDS -> STG with zero global-latency on the critical path.
    int r0[UNROLL];
    const bool full_first = (base + (UNROLL - 1) * step < total_vec4);
    if (full_first) {
        #pragma unroll
        for (int u = 0; u < UNROLL; u++)
            r0[u] = __ldg(&idx[(base + u * step) >> 4]);
    }

    // ------------- Handshake: sharded plain-load poll, tight cap -------------
    if (tid == 0) {
        volatile unsigned* flag = &g_go_arr[(blockIdx.x & (N_REGS - 1)) * FLAG_STRIDE];
        unsigned delay = 64u + ((blockIdx.x >> 5) & 7u) * 16u;
        while (*flag == 0u) {
            __nanosleep(delay);
            delay = min(delay + delay, 256u);
        }
    }
    __syncthreads();

    // Stage table into smem (__ldcg: L1-bypass, coherent with builders' L2 data).
    const float4* gt = reinterpret_cast<const float4*>(g_table);
    for (int i = tid; i < TAB_VEC4; i += THREADS)
        stab[i] = __ldcg(&gt[i]);
    __syncthreads();

    // ------------- Consumer phase: persistent grid-stride gather -------------
    // Element stride = GRID*THREADS (0 mod 16): c = t & 15 constant per thread,
    // stores fully coalesced, smem reads conflict-free.

    // First batch from the pre-loaded registers.
    if (full_first) {
        #pragma unroll
        for (int u = 0; u < UNROLL; u++)
            out[base + u * step] = stab[(r0[u] << 4) + ((base + u * step) & 15)];
        base += UNROLL * step;
    }

    // Main loop: batch 8 independent idx loads (MLP=8), then drain one-by-one
    // (stores are fire-and-forget; only the loads need batching). Keeps the
    // live register set small enough to avoid spills at the 42-reg cap.
    for (; base + (UNROLL - 1) * step < total_vec4; base += UNROLL * step) {
        int r[UNROLL];
        #pragma unroll
        for (int u = 0; u < UNROLL; u++)
            r[u] = __ldg(&idx[(base + u * step) >> 4]);
        #pragma unroll
        for (int u = 0; u < UNROLL; u++)
            out[base + u * step] = stab[(r[u] << 4) + ((base + u * step) & 15)];
    }
    for (; base < total_vec4; base += step) {
        int rr = __ldg(&idx[base >> 4]);
        out[base] = stab[(rr << 4) + (base & 15)];
    }

    // ------------- Reset flags for the next graph replay ---------------------
    __syncthreads();
    if (tid == 0) {
        unsigned old = atomicAdd(&g_done[0], 1u);
        if (old == (unsigned)(gridDim.x - 1)) {
            for (int f = 0; f < N_REGS; f++)
                *(volatile unsigned*)&g_go_arr[f * FLAG_STRIDE] = 0u;
            atomicExch(&g_ready[0], 0u);
            atomicExch(&g_done[0], 0u);
            __threadfence();
        }
    }
}

extern "C" void kernel_launch(void* const* d_in, const int* in_sizes, int n_in,
                              void* d_out, int out_size)
{
    const int*   idx  = (const int*)  d_in[0];
    const float* W1   = (const float*)d_in[1];
    const float* b1   = (const float*)d_in[2];
    const float* W2   = (const float*)d_in[3];
    const float* b2   = (const float*)d_in[4];
    const float* keys = (const float*)d_in[5];
    const float* temp = (const float*)d_in[6];
    const float* rv   = (const float*)d_in[7];

    const int B = in_sizes[0];
    const int total_vec4 = B * (BIT_WIDTH / 4);   // B * 16

    fused_kernel<<<GRID, THREADS>>>(idx, W1, b1, W2, b2, keys, temp, rv,
                                    (float4*)d_out, total_vec4);
}